// round 5
// baseline (speedup 1.0000x reference)
#include <cuda_runtime.h>
#include <cstdint>

// Problem constants
#define NB    8
#define NTOK  16384
#define NC    256
#define NWIN  2048    // B * (16x16 windows)
#define QKVW  768     // q(256) | k(256) | v(256)

// Scratch. All channel (k) dims are stored PERMUTED within 8-groups:
// position p holds original k = (p&1)*4 + (p>>1)  (i.e. order 0,4,1,5,2,6,3,7)
// so mma fragment pairs (k, k+4) are adjacent -> one LDS.64.
__device__ float g_qkv[(size_t)NWIN * 64 * QKVW];
__device__ float g_actq[(size_t)NWIN * 64 * 256];  // windowed, rounded, permuted query
__device__ float g_actx[(size_t)NWIN * 64 * 256];  // windowed, rounded, permuted x
__device__ float g_wqk[512 * 256];
__device__ float g_wv[256 * 256];
__device__ float g_wproj[256 * 256];

// ---------------------------------------------------------------------------
// tf32 helpers
// ---------------------------------------------------------------------------
__device__ __forceinline__ uint32_t f2tf(float f) {
    uint32_t u;
    asm("cvt.rna.tf32.f32 %0, %1;" : "=r"(u) : "f"(f));
    return u;
}
__device__ __forceinline__ float ftf(float f) {
    return __uint_as_float(f2tf(f));
}
__device__ __forceinline__ void mma_tf32(float c[4],
    uint32_t a0, uint32_t a1, uint32_t a2, uint32_t a3,
    uint32_t b0, uint32_t b1)
{
    asm volatile(
        "mma.sync.aligned.m16n8k8.row.col.f32.tf32.tf32.f32 "
        "{%0,%1,%2,%3},{%4,%5,%6,%7},{%8,%9},{%0,%1,%2,%3};"
        : "+f"(c[0]), "+f"(c[1]), "+f"(c[2]), "+f"(c[3])
        : "r"(a0), "r"(a1), "r"(a2), "r"(a3), "r"(b0), "r"(b1));
}
#define CPA16(dst, src) \
    asm volatile("cp.async.cg.shared.global [%0],[%1],16;" :: "r"(dst), "l"(src))
#define CP_COMMIT() asm volatile("cp.async.commit_group;")
#define CP_WAIT0()  asm volatile("cp.async.wait_group 0;" ::: "memory")

#define TSTRIDE 36
#define TILE_F  (128 * TSTRIDE)
#define BUF_F   (2 * TILE_F)
#define SMEM_MMA_BYTES (2 * BUF_F * 4)

// ---------------------------------------------------------------------------
// Pre-passes: round to tf32 + permute 8-groups (+ windowed gather for acts)
// dst 8-group = (s0,s4,s1,s5,s2,s6,s3,s7)
// ---------------------------------------------------------------------------
__global__ __launch_bounds__(256) void prep_act(
    const float* __restrict__ x, const float* __restrict__ query)
{
    const int tid = threadIdx.x;
    const float* src = blockIdx.y ? x : query;
    float* dst = blockIdx.y ? g_actx : g_actq;
    const int frow = blockIdx.x * 8 + (tid >> 5);
    const int lane = tid & 31;
    const int win = frow >> 6, s = frow & 63;
    const int b = win >> 8, g = win & 255;
    const int n = ((g >> 4) * 8 + (s >> 3)) * 128 + (g & 15) * 8 + (s & 7);
    const float4* sp = (const float4*)(src + ((long)b * NTOK + n) * 256 + lane * 8);
    float4 v0 = sp[0], v1 = sp[1];
    float4* dp = (float4*)(dst + (long)frow * 256 + lane * 8);
    dp[0] = make_float4(ftf(v0.x), ftf(v1.x), ftf(v0.y), ftf(v1.y));
    dp[1] = make_float4(ftf(v0.z), ftf(v1.z), ftf(v0.w), ftf(v1.w));
}

__global__ __launch_bounds__(256) void cvt_weights(
    const float* __restrict__ wqk, const float* __restrict__ wv,
    const float* __restrict__ wproj)
{
    const int t = blockIdx.x * 256 + threadIdx.x;   // 32768 threads, 8 floats each
    const int off = t * 8;
    const float* s; float* d;
    if (off < 131072)      { s = wqk + off;           d = g_wqk + off; }
    else if (off < 196608) { s = wv + off - 131072;   d = g_wv + off - 131072; }
    else                   { s = wproj + off - 196608; d = g_wproj + off - 196608; }
    float4 v0 = ((const float4*)s)[0], v1 = ((const float4*)s)[1];
    ((float4*)d)[0] = make_float4(ftf(v0.x), ftf(v1.x), ftf(v0.y), ftf(v1.y));
    ((float4*)d)[1] = make_float4(ftf(v0.z), ftf(v1.z), ftf(v0.w), ftf(v1.w));
}

// ---------------------------------------------------------------------------
// Kernel A (tf32 mma): Q|K|V GEMM. A from g_act (contiguous, permuted,
// rounded), B from permuted rounded weights. Zero CVT, float2 frag loads.
// Epilogue writes g_qkv rounded + permuted (mma N-index is natural channel
// space here because weight rows are natural -> apply channel->position map).
// ---------------------------------------------------------------------------
__global__ __launch_bounds__(256) void qkv_mma()
{
    extern __shared__ float sm[];
    const int tid = threadIdx.x;
    const int p   = blockIdx.x;
    const int cb  = blockIdx.y;

    const float* in = (cb < 4) ? g_actq : g_actx;
    const float* Wt = (cb < 4) ? (g_wqk + (long)cb * 128 * 256)
                               : (g_wv  + (long)(cb - 4) * 128 * 256);
    const int dstcol = (cb < 4) ? cb * 128 : 512 + (cb - 4) * 128;

    const int ldr = tid >> 1;
    const int ldc = (tid & 1) << 4;
    const float* a_src0 = in + (long)(p * 128 + ldr) * 256 + ldc;
    const float* b_src0 = Wt + (long)ldr * 256 + ldc;

    uint32_t smem_base = (uint32_t)__cvta_generic_to_shared(sm);
    uint32_t a_dst0 = smem_base + (uint32_t)(ldr * TSTRIDE + ldc) * 4;
    uint32_t b_dst0 = a_dst0 + TILE_F * 4;

    const int lane = tid & 31, w = tid >> 5;
    const int wm = (w >> 1) * 32;
    const int wn = (w & 1) * 64;
    const int gq = lane >> 2, tg = lane & 3;

    float acc[2][8][4];
    #pragma unroll
    for (int mt = 0; mt < 2; mt++)
        #pragma unroll
        for (int nt = 0; nt < 8; nt++)
            #pragma unroll
            for (int q = 0; q < 4; q++) acc[mt][nt][q] = 0.f;

    {
        #pragma unroll
        for (int i = 0; i < 4; i++) CPA16(a_dst0 + i * 16, a_src0 + i * 4);
        #pragma unroll
        for (int i = 0; i < 4; i++) CPA16(b_dst0 + i * 16, b_src0 + i * 4);
        CP_COMMIT();
    }

    for (int kb = 0; kb < 8; ++kb) {
        CP_WAIT0();
        __syncthreads();
        if (kb < 7) {
            uint32_t off = (uint32_t)(((kb + 1) & 1) * BUF_F * 4);
            const float* as = a_src0 + (kb + 1) * 32;
            const float* bs = b_src0 + (kb + 1) * 32;
            #pragma unroll
            for (int i = 0; i < 4; i++) CPA16(a_dst0 + off + i * 16, as + i * 4);
            #pragma unroll
            for (int i = 0; i < 4; i++) CPA16(b_dst0 + off + i * 16, bs + i * 4);
            CP_COMMIT();
        }
        const float* sA = sm + (kb & 1) * BUF_F;
        const float* sB = sA + TILE_F;

        #pragma unroll
        for (int ks = 0; ks < 4; ++ks) {
            const int k0 = ks * 8 + 2 * tg;
            uint32_t af[2][4];
            #pragma unroll
            for (int mt = 0; mt < 2; mt++) {
                const int r0 = wm + mt * 16;
                float2 lo = *(const float2*)&sA[(r0 + gq)     * TSTRIDE + k0];
                float2 hi = *(const float2*)&sA[(r0 + gq + 8) * TSTRIDE + k0];
                af[mt][0] = __float_as_uint(lo.x);
                af[mt][1] = __float_as_uint(hi.x);
                af[mt][2] = __float_as_uint(lo.y);
                af[mt][3] = __float_as_uint(hi.y);
            }
            #pragma unroll
            for (int nt = 0; nt < 8; nt++) {
                float2 bv = *(const float2*)&sB[(wn + nt * 8 + gq) * TSTRIDE + k0];
                uint32_t b0 = __float_as_uint(bv.x);
                uint32_t b1 = __float_as_uint(bv.y);
                mma_tf32(acc[0][nt], af[0][0], af[0][1], af[0][2], af[0][3], b0, b1);
                mma_tf32(acc[1][nt], af[1][0], af[1][1], af[1][2], af[1][3], b0, b1);
            }
        }
    }

    // epilogue: output channels (2tg, 2tg+1) -> permuted positions (pb, pb+2)
    const long row0 = (long)p * 128;
    const int pb = (tg & 1) * 4 + (tg >> 1);
    #pragma unroll
    for (int mt = 0; mt < 2; mt++) {
        #pragma unroll
        for (int nt = 0; nt < 8; nt++) {
            const int gb = dstcol + wn + nt * 8;
            const long r1 = row0 + wm + mt * 16 + gq;
            g_qkv[r1 * QKVW + gb + pb]           = ftf(acc[mt][nt][0]);
            g_qkv[r1 * QKVW + gb + pb + 2]       = ftf(acc[mt][nt][1]);
            g_qkv[(r1 + 8) * QKVW + gb + pb]     = ftf(acc[mt][nt][2]);
            g_qkv[(r1 + 8) * QKVW + gb + pb + 2] = ftf(acc[mt][nt][3]);
        }
    }
}

// ---------------------------------------------------------------------------
// Kernel B: per-window attention. Q/K/V arrive rounded + d-permuted.
// Scores mma: float2 frags, zero CVT. O-mma: V read by storage position ->
// mma output is ALREADY in permuted position space -> store columns directly.
// ---------------------------------------------------------------------------
#define SKR 260
#define PL  4232
#define RS  66
#define OFF_K     0
#define OFF_ATTN  16640
#define OFF_WPRE  (16640 + 8 * PL)
#define OFF_WPOST (OFF_WPRE + 64)
#define OFF_RSUM  (OFF_WPRE + 128)
#define SMEM_ATTN_F (OFF_RSUM + 512)
#define SMEM_ATTN_BYTES (SMEM_ATTN_F * 4)

__global__ __launch_bounds__(256) void attn_kernel(
    const float* __restrict__ W_pre, const float* __restrict__ W_post)
{
    extern __shared__ float sm[];
    float4* s_k4 = (float4*)(sm + OFF_K);
    float4* s_q4 = (float4*)(sm + OFF_ATTN);
    float*  s_attn  = sm + OFF_ATTN;
    float*  s_wpre  = sm + OFF_WPRE;
    float*  s_wpost = sm + OFF_WPOST;
    float*  s_rsum  = sm + OFF_RSUM;

    const int tid  = threadIdx.x;
    const int lane = tid & 31;
    const int h    = tid >> 5;
    const int gq = lane >> 2, tg = lane & 3;
    const int h32 = h * 32;
    const long rowbase = (long)blockIdx.x * 64;
    const float4* qkv4 = (const float4*)g_qkv;

    for (int idx = tid; idx < 64 * 64; idx += 256) {
        int s = idx >> 6, c4 = idx & 63;
        s_q4[s * 65 + c4] = qkv4[(rowbase + s) * 192 + c4];
        s_k4[s * 65 + c4] = qkv4[(rowbase + s) * 192 + 64 + c4];
    }
    if (tid < 64) { s_wpre[tid] = W_pre[tid]; s_wpost[tid] = W_post[tid]; }
    __syncthreads();

    // ---- scores: S_h = Q_h @ K_h^T  (M=64,N=64,K=32; d permuted both sides)
    const float* sq = sm + OFF_ATTN;
    const float* sk = sm + OFF_K;
    float acc[4][8][4];
    #pragma unroll
    for (int mt = 0; mt < 4; mt++)
        #pragma unroll
        for (int nt = 0; nt < 8; nt++)
            #pragma unroll
            for (int q = 0; q < 4; q++) acc[mt][nt][q] = 0.f;

    #pragma unroll
    for (int ks = 0; ks < 4; ++ks) {
        const int k0 = h32 + ks * 8 + 2 * tg;
        uint32_t a[4][4];
        #pragma unroll
        for (int mt = 0; mt < 4; mt++) {
            const int r0 = mt * 16;
            float2 lo = *(const float2*)&sq[(r0 + gq)     * SKR + k0];
            float2 hi = *(const float2*)&sq[(r0 + gq + 8) * SKR + k0];
            a[mt][0] = __float_as_uint(lo.x);
            a[mt][1] = __float_as_uint(hi.x);
            a[mt][2] = __float_as_uint(lo.y);
            a[mt][3] = __float_as_uint(hi.y);
        }
        #pragma unroll
        for (int nt = 0; nt < 8; nt++) {
            float2 bv = *(const float2*)&sk[(nt * 8 + gq) * SKR + k0];
            uint32_t b0 = __float_as_uint(bv.x);
            uint32_t b1 = __float_as_uint(bv.y);
            #pragma unroll
            for (int mt = 0; mt < 4; mt++)
                mma_tf32(acc[mt][nt], a[mt][0], a[mt][1], a[mt][2], a[mt][3], b0, b1);
        }
    }
    __syncthreads();

    // STS scores (scaled, natural kseq order); stage V over K buffer
    const float scale = 0.17677669529663687f;
    float* pl = sm + OFF_ATTN + h * PL;
    #pragma unroll
    for (int mt = 0; mt < 4; mt++) {
        #pragma unroll
        for (int nt = 0; nt < 8; nt++) {
            const int q0 = mt * 16 + gq, c = nt * 8 + 2 * tg;
            *(float2*)&pl[q0 * RS + c] =
                make_float2(acc[mt][nt][0] * scale, acc[mt][nt][1] * scale);
            *(float2*)&pl[(q0 + 8) * RS + c] =
                make_float2(acc[mt][nt][2] * scale, acc[mt][nt][3] * scale);
        }
    }
    for (int idx = tid; idx < 64 * 64; idx += 256) {
        int s = idx >> 6, c4 = idx & 63;
        s_k4[s * 65 + c4] = qkv4[(rowbase + s) * 192 + 128 + c4];   // V
    }
    __syncthreads();

    // ---- pre-mix + exp ----
    #pragma unroll 1
    for (int i = 0; i < 16; i++) {
        int pidx = tid + (i << 8);
        int q = pidx >> 6, k = pidx & 63;
        float av[8], m[8];
        #pragma unroll
        for (int hh = 0; hh < 8; hh++) av[hh] = s_attn[hh * PL + q * RS + k];
        #pragma unroll
        for (int hh = 0; hh < 8; hh++) {
            float s = 0.f;
            #pragma unroll
            for (int h2 = 0; h2 < 8; h2++) s += av[h2] * s_wpre[hh * 8 + h2];
            m[hh] = __expf(s);
        }
        #pragma unroll
        for (int hh = 0; hh < 8; hh++) s_attn[hh * PL + q * RS + k] = m[hh];
    }
    __syncthreads();

    // ---- softmax denominator ----
    #pragma unroll
    for (int i = 0; i < 2; i++) {
        int task = tid + (i << 8);
        int q = task >> 3, hh = task & 7;
        float s = 0.f;
        #pragma unroll 8
        for (int k = 0; k < 64; k++) s += s_attn[hh * PL + q * RS + k];
        s_rsum[task] = 1.0f / s;
    }
    __syncthreads();

    // ---- normalize + post-mix ----
    #pragma unroll 1
    for (int i = 0; i < 16; i++) {
        int pidx = tid + (i << 8);
        int q = pidx >> 6, k = pidx & 63;
        float av[8], m[8];
        #pragma unroll
        for (int hh = 0; hh < 8; hh++)
            av[hh] = s_attn[hh * PL + q * RS + k] * s_rsum[q * 8 + hh];
        #pragma unroll
        for (int hh = 0; hh < 8; hh++) {
            float s = 0.f;
            #pragma unroll
            for (int h2 = 0; h2 < 8; h2++) s += av[h2] * s_wpost[hh * 8 + h2];
            m[hh] = s;
        }
        #pragma unroll
        for (int hh = 0; hh < 8; hh++) s_attn[hh * PL + q * RS + k] = m[hh];
    }
    __syncthreads();

    // ---- O_h = A_h @ V_h  (M=64, N=32, K=64; V rounded -> no B CVT) ----
    float acc2[4][4][4];
    #pragma unroll
    for (int mt = 0; mt < 4; mt++)
        #pragma unroll
        for (int nt = 0; nt < 4; nt++)
            #pragma unroll
            for (int q = 0; q < 4; q++) acc2[mt][nt][q] = 0.f;

    #pragma unroll
    for (int ks = 0; ks < 8; ++ks) {
        const int k0 = ks * 8;
        uint32_t a[4][4];
        #pragma unroll
        for (int mt = 0; mt < 4; mt++) {
            const int r0 = mt * 16;
            a[mt][0] = f2tf(pl[(r0 + gq)     * RS + k0 + tg]);
            a[mt][1] = f2tf(pl[(r0 + gq + 8) * RS + k0 + tg]);
            a[mt][2] = f2tf(pl[(r0 + gq)     * RS + k0 + tg + 4]);
            a[mt][3] = f2tf(pl[(r0 + gq + 8) * RS + k0 + tg + 4]);
        }
        #pragma unroll
        for (int nt = 0; nt < 4; nt++) {
            const int nb = nt * 8;
            uint32_t b0 = __float_as_uint(sk[(k0 + tg)     * SKR + h32 + nb + gq]);
            uint32_t b1 = __float_as_uint(sk[(k0 + tg + 4) * SKR + h32 + nb + gq]);
            #pragma unroll
            for (int mt = 0; mt < 4; mt++)
                mma_tf32(acc2[mt][nt], a[mt][0], a[mt][1], a[mt][2], a[mt][3], b0, b1);
        }
    }

    // epilogue: V was indexed by storage POSITION, so mma output columns are
    // already in permuted position space -> store directly (float2), no remap.
    #pragma unroll
    for (int mt = 0; mt < 4; mt++) {
        #pragma unroll
        for (int nt = 0; nt < 4; nt++) {
            const int col = h32 + nt * 8 + 2 * tg;
            const long r1 = rowbase + mt * 16 + gq;
            *(float2*)(g_qkv + r1 * QKVW + col) =
                make_float2(ftf(acc2[mt][nt][0]), ftf(acc2[mt][nt][1]));
            *(float2*)(g_qkv + (r1 + 8) * QKVW + col) =
                make_float2(ftf(acc2[mt][nt][2]), ftf(acc2[mt][nt][3]));
        }
    }
}

// ---------------------------------------------------------------------------
// Kernel C (tf32 mma): out = unwindow(O) @ W_proj^T + b_proj. Zero CVT.
// ---------------------------------------------------------------------------
__global__ __launch_bounds__(256) void proj_mma(
    const float* __restrict__ b_proj, float* __restrict__ out)
{
    extern __shared__ float sm[];
    const int tid = threadIdx.x;
    const long row0 = (long)blockIdx.x * 128;
    const int colb = blockIdx.y * 128;

    const int ldr = tid >> 1;
    const int ldc = (tid & 1) << 4;
    long row = row0 + ldr;
    int b = (int)(row >> 14);
    int n = (int)(row & 16383);
    int i = n >> 7, j = n & 127;
    int srcrow = ((b << 8) + (i >> 3) * 16 + (j >> 3)) * 64 + (i & 7) * 8 + (j & 7);
    const float* a_src0 = g_qkv + (long)srcrow * QKVW + ldc;
    const float* b_src0 = g_wproj + (long)(colb + ldr) * 256 + ldc;

    uint32_t smem_base = (uint32_t)__cvta_generic_to_shared(sm);
    uint32_t a_dst0 = smem_base + (uint32_t)(ldr * TSTRIDE + ldc) * 4;
    uint32_t b_dst0 = a_dst0 + TILE_F * 4;

    const int lane = tid & 31, w = tid >> 5;
    const int wm = (w >> 1) * 32;
    const int wn = (w & 1) * 64;
    const int gq = lane >> 2, tg = lane & 3;

    float acc[2][8][4];
    #pragma unroll
    for (int mt = 0; mt < 2; mt++)
        #pragma unroll
        for (int nt = 0; nt < 8; nt++)
            #pragma unroll
            for (int q = 0; q < 4; q++) acc[mt][nt][q] = 0.f;

    {
        #pragma unroll
        for (int k = 0; k < 4; k++) CPA16(a_dst0 + k * 16, a_src0 + k * 4);
        #pragma unroll
        for (int k = 0; k < 4; k++) CPA16(b_dst0 + k * 16, b_src0 + k * 4);
        CP_COMMIT();
    }

    for (int kb = 0; kb < 8; ++kb) {
        CP_WAIT0();
        __syncthreads();
        if (kb < 7) {
            uint32_t off = (uint32_t)(((kb + 1) & 1) * BUF_F * 4);
            const float* as = a_src0 + (kb + 1) * 32;
            const float* bs = b_src0 + (kb + 1) * 32;
            #pragma unroll
            for (int k = 0; k < 4; k++) CPA16(a_dst0 + off + k * 16, as + k * 4);
            #pragma unroll
            for (int k = 0; k < 4; k++) CPA16(b_dst0 + off + k * 16, bs + k * 4);
            CP_COMMIT();
        }
        const float* sA = sm + (kb & 1) * BUF_F;
        const float* sB = sA + TILE_F;

        #pragma unroll
        for (int ks = 0; ks < 4; ++ks) {
            const int k0 = ks * 8 + 2 * tg;
            uint32_t af[2][4];
            #pragma unroll
            for (int mt = 0; mt < 2; mt++) {
                const int r0 = wm + mt * 16;
                float2 lo = *(const float2*)&sA[(r0 + gq)     * TSTRIDE + k0];
                float2 hi = *(const float2*)&sA[(r0 + gq + 8) * TSTRIDE + k0];
                af[mt][0] = __float_as_uint(lo.x);
                af[mt][1] = __float_as_uint(hi.x);
                af[mt][2] = __float_as_uint(lo.y);
                af[mt][3] = __float_as_uint(hi.y);
            }
            #pragma unroll
            for (int nt = 0; nt < 8; nt++) {
                float2 bv = *(const float2*)&sB[(wn + nt * 8 + gq) * TSTRIDE + k0];
                uint32_t b0 = __float_as_uint(bv.x);
                uint32_t b1 = __float_as_uint(bv.y);
                mma_tf32(acc[0][nt], af[0][0], af[0][1], af[0][2], af[0][3], b0, b1);
                mma_tf32(acc[1][nt], af[1][0], af[1][1], af[1][2], af[1][3], b0, b1);
            }
        }
    }

    #pragma unroll
    for (int mt = 0; mt < 2; mt++) {
        #pragma unroll
        for (int nt = 0; nt < 8; nt++) {
            const int col = colb + wn + nt * 8 + tg * 2;
            const float2 bv = *(const float2*)(b_proj + col);
            const long r1 = row0 + wm + mt * 16 + gq;
            *(float2*)(out + r1 * NC + col) =
                make_float2(acc[mt][nt][0] + bv.x, acc[mt][nt][1] + bv.y);
            *(float2*)(out + (r1 + 8) * NC + col) =
                make_float2(acc[mt][nt][2] + bv.x, acc[mt][nt][3] + bv.y);
        }
    }
}

// ---------------------------------------------------------------------------
extern "C" void kernel_launch(void* const* d_in, const int* in_sizes, int n_in,
                              void* d_out, int out_size)
{
    const float* x      = (const float*)d_in[0];
    const float* query  = (const float*)d_in[1];
    const float* W_qk   = (const float*)d_in[2];
    const float* W_v    = (const float*)d_in[3];
    const float* W_proj = (const float*)d_in[4];
    const float* b_proj = (const float*)d_in[5];
    const float* W_pre  = (const float*)d_in[6];
    const float* W_post = (const float*)d_in[7];
    float* out = (float*)d_out;

    cudaFuncSetAttribute(qkv_mma,  cudaFuncAttributeMaxDynamicSharedMemorySize, SMEM_MMA_BYTES);
    cudaFuncSetAttribute(attn_kernel, cudaFuncAttributeMaxDynamicSharedMemorySize, SMEM_ATTN_BYTES);
    cudaFuncSetAttribute(proj_mma, cudaFuncAttributeMaxDynamicSharedMemorySize, SMEM_MMA_BYTES);

    cvt_weights<<<128, 256>>>(W_qk, W_v, W_proj);
    prep_act<<<dim3(16384, 2), 256>>>(x, query);
    qkv_mma<<<dim3(NWIN / 2, 6), 256, SMEM_MMA_BYTES>>>();
    attn_kernel<<<NWIN, 256, SMEM_ATTN_BYTES>>>(W_pre, W_post);
    proj_mma<<<dim3(NWIN / 2, 2), 256, SMEM_MMA_BYTES>>>(b_proj, out);
}

// round 6
// speedup vs baseline: 1.1707x; 1.1707x over previous
#include <cuda_runtime.h>
#include <cstdint>

// Problem constants
#define NB    8
#define NTOK  16384
#define NC    256
#define NWIN  2048    // B * (16x16 windows)
#define QKVW  768     // q(256) | k(256) | v(256)

// g_qkv channel dims stored PERMUTED within 8-groups:
// position p holds channel c(p) = (p&1)*4 + (p>>1)   (order 0,4,1,5,2,6,3,7)
__device__ float g_qkv[(size_t)NWIN * 64 * QKVW];
__device__ float g_wqk[512 * 256];     // rounded + permuted
__device__ float g_wv[256 * 256];
__device__ float g_wproj[256 * 256];

// ---------------------------------------------------------------------------
__device__ __forceinline__ uint32_t f2tf(float f) {
    uint32_t u;
    asm("cvt.rna.tf32.f32 %0, %1;" : "=r"(u) : "f"(f));
    return u;
}
__device__ __forceinline__ float ftf(float f) {
    return __uint_as_float(f2tf(f));
}
__device__ __forceinline__ void mma_tf32(float c[4],
    uint32_t a0, uint32_t a1, uint32_t a2, uint32_t a3,
    uint32_t b0, uint32_t b1)
{
    asm volatile(
        "mma.sync.aligned.m16n8k8.row.col.f32.tf32.tf32.f32 "
        "{%0,%1,%2,%3},{%4,%5,%6,%7},{%8,%9},{%0,%1,%2,%3};"
        : "+f"(c[0]), "+f"(c[1]), "+f"(c[2]), "+f"(c[3])
        : "r"(a0), "r"(a1), "r"(a2), "r"(a3), "r"(b0), "r"(b1));
}
#define CPA16(dst, src) \
    asm volatile("cp.async.cg.shared.global [%0],[%1],16;" :: "r"(dst), "l"(src))
#define CP_COMMIT() asm volatile("cp.async.commit_group;")
#define CP_WAIT0()  asm volatile("cp.async.wait_group 0;" ::: "memory")

#define TSTRIDE 36
#define TILE_F  (128 * TSTRIDE)
#define BUF_F   (2 * TILE_F)
#define SMEM_MMA_BYTES (2 * BUF_F * 4)

// ---------------------------------------------------------------------------
// Weights: round to tf32 + permute 8-groups
// ---------------------------------------------------------------------------
__global__ __launch_bounds__(256) void cvt_weights(
    const float* __restrict__ wqk, const float* __restrict__ wv,
    const float* __restrict__ wproj)
{
    const int t = blockIdx.x * 256 + threadIdx.x;
    const int off = t * 8;
    const float* s; float* d;
    if (off < 131072)      { s = wqk + off;           d = g_wqk + off; }
    else if (off < 196608) { s = wv + off - 131072;   d = g_wv + off - 131072; }
    else                   { s = wproj + off - 196608; d = g_wproj + off - 196608; }
    float4 v0 = ((const float4*)s)[0], v1 = ((const float4*)s)[1];
    ((float4*)d)[0] = make_float4(ftf(v0.x), ftf(v1.x), ftf(v0.y), ftf(v1.y));
    ((float4*)d)[1] = make_float4(ftf(v0.z), ftf(v1.z), ftf(v0.w), ftf(v1.w));
}

// ---------------------------------------------------------------------------
// Kernel A: Q|K|V GEMM. A gathered raw (CVT on A frags), B permuted/rounded
// (zero CVT, float2 frags). Epilogue writes g_qkv rounded + permuted.
// ---------------------------------------------------------------------------
__global__ __launch_bounds__(256) void qkv_mma(
    const float* __restrict__ x, const float* __restrict__ query)
{
    extern __shared__ float sm[];
    const int tid = threadIdx.x;
    const int p   = blockIdx.x;
    const int cb  = blockIdx.y;

    const float* in = (cb < 4) ? query : x;
    const float* Wt = (cb < 4) ? (g_wqk + (long)cb * 128 * 256)
                               : (g_wv  + (long)(cb - 4) * 128 * 256);
    const int dstcol = (cb < 4) ? cb * 128 : 512 + (cb - 4) * 128;

    const int ldr = tid >> 1;
    const int ldc = (tid & 1) << 4;
    int win = p * 2 + (ldr >> 6);
    int s   = ldr & 63;
    int b   = win >> 8, g = win & 255;
    int n   = ((g >> 4) * 8 + (s >> 3)) * 128 + (g & 15) * 8 + (s & 7);
    const float* a_src0 = in + ((long)b * NTOK + n) * 256 + ldc;
    const float* b_src0 = Wt + (long)ldr * 256 + ldc;

    uint32_t smem_base = (uint32_t)__cvta_generic_to_shared(sm);
    uint32_t a_dst0 = smem_base + (uint32_t)(ldr * TSTRIDE + ldc) * 4;
    uint32_t b_dst0 = a_dst0 + TILE_F * 4;

    const int lane = tid & 31, w = tid >> 5;
    const int wm = (w >> 1) * 32;
    const int wn = (w & 1) * 64;
    const int gq = lane >> 2, tg = lane & 3;

    float acc[2][8][4];
    #pragma unroll
    for (int mt = 0; mt < 2; mt++)
        #pragma unroll
        for (int nt = 0; nt < 8; nt++)
            #pragma unroll
            for (int q = 0; q < 4; q++) acc[mt][nt][q] = 0.f;

    {
        #pragma unroll
        for (int i = 0; i < 4; i++) CPA16(a_dst0 + i * 16, a_src0 + i * 4);
        #pragma unroll
        for (int i = 0; i < 4; i++) CPA16(b_dst0 + i * 16, b_src0 + i * 4);
        CP_COMMIT();
    }

    for (int kb = 0; kb < 8; ++kb) {
        CP_WAIT0();
        __syncthreads();
        if (kb < 7) {
            uint32_t off = (uint32_t)(((kb + 1) & 1) * BUF_F * 4);
            const float* as = a_src0 + (kb + 1) * 32;
            const float* bs = b_src0 + (kb + 1) * 32;
            #pragma unroll
            for (int i = 0; i < 4; i++) CPA16(a_dst0 + off + i * 16, as + i * 4);
            #pragma unroll
            for (int i = 0; i < 4; i++) CPA16(b_dst0 + off + i * 16, bs + i * 4);
            CP_COMMIT();
        }
        const float* sA = sm + (kb & 1) * BUF_F;
        const float* sB = sA + TILE_F;

        #pragma unroll
        for (int ks = 0; ks < 4; ++ks) {
            const int k0n = ks * 8;            // natural channels (A)
            const int k0p = ks * 8 + 2 * tg;   // permuted positions (B)
            uint32_t af[2][4];
            #pragma unroll
            for (int mt = 0; mt < 2; mt++) {
                const int r0 = wm + mt * 16;
                af[mt][0] = f2tf(sA[(r0 + gq)     * TSTRIDE + k0n + tg]);
                af[mt][1] = f2tf(sA[(r0 + gq + 8) * TSTRIDE + k0n + tg]);
                af[mt][2] = f2tf(sA[(r0 + gq)     * TSTRIDE + k0n + tg + 4]);
                af[mt][3] = f2tf(sA[(r0 + gq + 8) * TSTRIDE + k0n + tg + 4]);
            }
            #pragma unroll
            for (int nt = 0; nt < 8; nt++) {
                float2 bv = *(const float2*)&sB[(wn + nt * 8 + gq) * TSTRIDE + k0p];
                uint32_t b0 = __float_as_uint(bv.x);   // channel k0n+tg
                uint32_t b1 = __float_as_uint(bv.y);   // channel k0n+tg+4
                mma_tf32(acc[0][nt], af[0][0], af[0][1], af[0][2], af[0][3], b0, b1);
                mma_tf32(acc[1][nt], af[1][0], af[1][1], af[1][2], af[1][3], b0, b1);
            }
        }
    }

    // epilogue: natural out channels (2tg,2tg+1) -> permuted positions (pb,pb+2)
    const long row0 = (long)p * 128;
    const int pb = (tg & 1) * 4 + (tg >> 1);
    #pragma unroll
    for (int mt = 0; mt < 2; mt++) {
        #pragma unroll
        for (int nt = 0; nt < 8; nt++) {
            const int gb = dstcol + wn + nt * 8;
            const long r1 = row0 + wm + mt * 16 + gq;
            g_qkv[r1 * QKVW + gb + pb]           = ftf(acc[mt][nt][0]);
            g_qkv[r1 * QKVW + gb + pb + 2]       = ftf(acc[mt][nt][1]);
            g_qkv[(r1 + 8) * QKVW + gb + pb]     = ftf(acc[mt][nt][2]);
            g_qkv[(r1 + 8) * QKVW + gb + pb + 2] = ftf(acc[mt][nt][3]);
        }
    }
}

// ---------------------------------------------------------------------------
// Kernel B: per-window attention, 512 threads = 16 warps = 2 warps/head
// (warp w: head w>>1, q-half w&1). Same smem as before; occupancy-driven.
// ---------------------------------------------------------------------------
#define SKR 260
#define PL  4232
#define RS  66
#define OFF_K     0
#define OFF_ATTN  16640
#define OFF_WPRE  (16640 + 8 * PL)
#define OFF_WPOST (OFF_WPRE + 64)
#define OFF_RSUM  (OFF_WPRE + 128)
#define SMEM_ATTN_F (OFF_RSUM + 512)
#define SMEM_ATTN_BYTES (SMEM_ATTN_F * 4)

__global__ __launch_bounds__(512) void attn_kernel(
    const float* __restrict__ W_pre, const float* __restrict__ W_post)
{
    extern __shared__ float sm[];
    float4* s_k4 = (float4*)(sm + OFF_K);
    float4* s_q4 = (float4*)(sm + OFF_ATTN);
    float*  s_attn  = sm + OFF_ATTN;
    float*  s_wpre  = sm + OFF_WPRE;
    float*  s_wpost = sm + OFF_WPOST;
    float*  s_rsum  = sm + OFF_RSUM;

    const int tid  = threadIdx.x;
    const int lane = tid & 31;
    const int w    = tid >> 5;
    const int h    = w >> 1;        // head 0..7
    const int mh   = (w & 1) * 32;  // q-half base row
    const int gq = lane >> 2, tg = lane & 3;
    const int h32 = h * 32;
    const long rowbase = (long)blockIdx.x * 64;
    const float4* qkv4 = (const float4*)g_qkv;

    for (int idx = tid; idx < 64 * 64; idx += 512) {
        int s = idx >> 6, c4 = idx & 63;
        s_q4[s * 65 + c4] = qkv4[(rowbase + s) * 192 + c4];
        s_k4[s * 65 + c4] = qkv4[(rowbase + s) * 192 + 64 + c4];
    }
    if (tid < 64) { s_wpre[tid] = W_pre[tid]; s_wpost[tid] = W_post[tid]; }
    __syncthreads();

    // ---- scores: S_h[mh..mh+32] = Q_h @ K_h^T (M=32,N=64,K=32; permuted d)
    const float* sq = sm + OFF_ATTN;
    const float* sk = sm + OFF_K;
    float acc[2][8][4];
    #pragma unroll
    for (int mt = 0; mt < 2; mt++)
        #pragma unroll
        for (int nt = 0; nt < 8; nt++)
            #pragma unroll
            for (int q = 0; q < 4; q++) acc[mt][nt][q] = 0.f;

    #pragma unroll
    for (int ks = 0; ks < 4; ++ks) {
        const int k0 = h32 + ks * 8 + 2 * tg;
        uint32_t a[2][4];
        #pragma unroll
        for (int mt = 0; mt < 2; mt++) {
            const int r0 = mh + mt * 16;
            float2 lo = *(const float2*)&sq[(r0 + gq)     * SKR + k0];
            float2 hi = *(const float2*)&sq[(r0 + gq + 8) * SKR + k0];
            a[mt][0] = __float_as_uint(lo.x);
            a[mt][1] = __float_as_uint(hi.x);
            a[mt][2] = __float_as_uint(lo.y);
            a[mt][3] = __float_as_uint(hi.y);
        }
        #pragma unroll
        for (int nt = 0; nt < 8; nt++) {
            float2 bv = *(const float2*)&sk[(nt * 8 + gq) * SKR + k0];
            uint32_t b0 = __float_as_uint(bv.x);
            uint32_t b1 = __float_as_uint(bv.y);
            #pragma unroll
            for (int mt = 0; mt < 2; mt++)
                mma_tf32(acc[mt][nt], a[mt][0], a[mt][1], a[mt][2], a[mt][3], b0, b1);
        }
    }
    __syncthreads();

    // STS scores (scaled); stage V over K buffer
    const float scale = 0.17677669529663687f;
    float* pl = sm + OFF_ATTN + h * PL;
    #pragma unroll
    for (int mt = 0; mt < 2; mt++) {
        #pragma unroll
        for (int nt = 0; nt < 8; nt++) {
            const int q0 = mh + mt * 16 + gq, c = nt * 8 + 2 * tg;
            *(float2*)&pl[q0 * RS + c] =
                make_float2(acc[mt][nt][0] * scale, acc[mt][nt][1] * scale);
            *(float2*)&pl[(q0 + 8) * RS + c] =
                make_float2(acc[mt][nt][2] * scale, acc[mt][nt][3] * scale);
        }
    }
    for (int idx = tid; idx < 64 * 64; idx += 512) {
        int s = idx >> 6, c4 = idx & 63;
        s_k4[s * 65 + c4] = qkv4[(rowbase + s) * 192 + 128 + c4];   // V
    }
    __syncthreads();

    // ---- pre-mix + exp (4096 (q,k) pairs over 512 threads) ----
    #pragma unroll 1
    for (int i = 0; i < 8; i++) {
        int pidx = tid + (i << 9);
        int q = pidx >> 6, k = pidx & 63;
        float av[8], m[8];
        #pragma unroll
        for (int hh = 0; hh < 8; hh++) av[hh] = s_attn[hh * PL + q * RS + k];
        #pragma unroll
        for (int hh = 0; hh < 8; hh++) {
            float s = 0.f;
            #pragma unroll
            for (int h2 = 0; h2 < 8; h2++) s += av[h2] * s_wpre[hh * 8 + h2];
            m[hh] = __expf(s);
        }
        #pragma unroll
        for (int hh = 0; hh < 8; hh++) s_attn[hh * PL + q * RS + k] = m[hh];
    }
    __syncthreads();

    // ---- softmax denominator (512 tasks = 64q x 8h) ----
    {
        int q = tid >> 3, hh = tid & 7;
        float s = 0.f;
        #pragma unroll 8
        for (int k = 0; k < 64; k++) s += s_attn[hh * PL + q * RS + k];
        s_rsum[tid] = 1.0f / s;
    }
    __syncthreads();

    // ---- normalize + post-mix ----
    #pragma unroll 1
    for (int i = 0; i < 8; i++) {
        int pidx = tid + (i << 9);
        int q = pidx >> 6, k = pidx & 63;
        float av[8], m[8];
        #pragma unroll
        for (int hh = 0; hh < 8; hh++)
            av[hh] = s_attn[hh * PL + q * RS + k] * s_rsum[q * 8 + hh];
        #pragma unroll
        for (int hh = 0; hh < 8; hh++) {
            float s = 0.f;
            #pragma unroll
            for (int h2 = 0; h2 < 8; h2++) s += av[h2] * s_wpost[hh * 8 + h2];
            m[hh] = s;
        }
        #pragma unroll
        for (int hh = 0; hh < 8; hh++) s_attn[hh * PL + q * RS + k] = m[hh];
    }
    __syncthreads();

    // ---- O_h[mh..mh+32] = A_h @ V_h (M=32,N=32,K=64; V rounded, no B CVT)
    float acc2[2][4][4];
    #pragma unroll
    for (int mt = 0; mt < 2; mt++)
        #pragma unroll
        for (int nt = 0; nt < 4; nt++)
            #pragma unroll
            for (int q = 0; q < 4; q++) acc2[mt][nt][q] = 0.f;

    #pragma unroll
    for (int ks = 0; ks < 8; ++ks) {
        const int k0 = ks * 8;
        uint32_t a[2][4];
        #pragma unroll
        for (int mt = 0; mt < 2; mt++) {
            const int r0 = mh + mt * 16;
            a[mt][0] = f2tf(pl[(r0 + gq)     * RS + k0 + tg]);
            a[mt][1] = f2tf(pl[(r0 + gq + 8) * RS + k0 + tg]);
            a[mt][2] = f2tf(pl[(r0 + gq)     * RS + k0 + tg + 4]);
            a[mt][3] = f2tf(pl[(r0 + gq + 8) * RS + k0 + tg + 4]);
        }
        #pragma unroll
        for (int nt = 0; nt < 4; nt++) {
            const int nb = nt * 8;
            uint32_t b0 = __float_as_uint(sk[(k0 + tg)     * SKR + h32 + nb + gq]);
            uint32_t b1 = __float_as_uint(sk[(k0 + tg + 4) * SKR + h32 + nb + gq]);
            #pragma unroll
            for (int mt = 0; mt < 2; mt++)
                mma_tf32(acc2[mt][nt], a[mt][0], a[mt][1], a[mt][2], a[mt][3], b0, b1);
        }
    }

    // epilogue: V indexed by storage POSITION -> output already permuted space
    #pragma unroll
    for (int mt = 0; mt < 2; mt++) {
        #pragma unroll
        for (int nt = 0; nt < 4; nt++) {
            const int col = h32 + nt * 8 + 2 * tg;
            const long r1 = rowbase + mh + mt * 16 + gq;
            *(float2*)(g_qkv + r1 * QKVW + col) =
                make_float2(ftf(acc2[mt][nt][0]), ftf(acc2[mt][nt][1]));
            *(float2*)(g_qkv + (r1 + 8) * QKVW + col) =
                make_float2(ftf(acc2[mt][nt][2]), ftf(acc2[mt][nt][3]));
        }
    }
}

// ---------------------------------------------------------------------------
// Kernel C: out = unwindow(O) @ W_proj^T + b_proj. Zero CVT (both permuted).
// ---------------------------------------------------------------------------
__global__ __launch_bounds__(256) void proj_mma(
    const float* __restrict__ b_proj, float* __restrict__ out)
{
    extern __shared__ float sm[];
    const int tid = threadIdx.x;
    const long row0 = (long)blockIdx.x * 128;
    const int colb = blockIdx.y * 128;

    const int ldr = tid >> 1;
    const int ldc = (tid & 1) << 4;
    long row = row0 + ldr;
    int b = (int)(row >> 14);
    int n = (int)(row & 16383);
    int i = n >> 7, j = n & 127;
    int srcrow = ((b << 8) + (i >> 3) * 16 + (j >> 3)) * 64 + (i & 7) * 8 + (j & 7);
    const float* a_src0 = g_qkv + (long)srcrow * QKVW + ldc;
    const float* b_src0 = g_wproj + (long)(colb + ldr) * 256 + ldc;

    uint32_t smem_base = (uint32_t)__cvta_generic_to_shared(sm);
    uint32_t a_dst0 = smem_base + (uint32_t)(ldr * TSTRIDE + ldc) * 4;
    uint32_t b_dst0 = a_dst0 + TILE_F * 4;

    const int lane = tid & 31, w = tid >> 5;
    const int wm = (w >> 1) * 32;
    const int wn = (w & 1) * 64;
    const int gq = lane >> 2, tg = lane & 3;

    float acc[2][8][4];
    #pragma unroll
    for (int mt = 0; mt < 2; mt++)
        #pragma unroll
        for (int nt = 0; nt < 8; nt++)
            #pragma unroll
            for (int q = 0; q < 4; q++) acc[mt][nt][q] = 0.f;

    {
        #pragma unroll
        for (int k = 0; k < 4; k++) CPA16(a_dst0 + k * 16, a_src0 + k * 4);
        #pragma unroll
        for (int k = 0; k < 4; k++) CPA16(b_dst0 + k * 16, b_src0 + k * 4);
        CP_COMMIT();
    }

    for (int kb = 0; kb < 8; ++kb) {
        CP_WAIT0();
        __syncthreads();
        if (kb < 7) {
            uint32_t off = (uint32_t)(((kb + 1) & 1) * BUF_F * 4);
            const float* as = a_src0 + (kb + 1) * 32;
            const float* bs = b_src0 + (kb + 1) * 32;
            #pragma unroll
            for (int k = 0; k < 4; k++) CPA16(a_dst0 + off + k * 16, as + k * 4);
            #pragma unroll
            for (int k = 0; k < 4; k++) CPA16(b_dst0 + off + k * 16, bs + k * 4);
            CP_COMMIT();
        }
        const float* sA = sm + (kb & 1) * BUF_F;
        const float* sB = sA + TILE_F;

        #pragma unroll
        for (int ks = 0; ks < 4; ++ks) {
            const int k0 = ks * 8 + 2 * tg;   // positions (both sides permuted)
            uint32_t af[2][4];
            #pragma unroll
            for (int mt = 0; mt < 2; mt++) {
                const int r0 = wm + mt * 16;
                float2 lo = *(const float2*)&sA[(r0 + gq)     * TSTRIDE + k0];
                float2 hi = *(const float2*)&sA[(r0 + gq + 8) * TSTRIDE + k0];
                af[mt][0] = __float_as_uint(lo.x);
                af[mt][1] = __float_as_uint(hi.x);
                af[mt][2] = __float_as_uint(lo.y);
                af[mt][3] = __float_as_uint(hi.y);
            }
            #pragma unroll
            for (int nt = 0; nt < 8; nt++) {
                float2 bv = *(const float2*)&sB[(wn + nt * 8 + gq) * TSTRIDE + k0];
                uint32_t b0 = __float_as_uint(bv.x);
                uint32_t b1 = __float_as_uint(bv.y);
                mma_tf32(acc[0][nt], af[0][0], af[0][1], af[0][2], af[0][3], b0, b1);
                mma_tf32(acc[1][nt], af[1][0], af[1][1], af[1][2], af[1][3], b0, b1);
            }
        }
    }

    #pragma unroll
    for (int mt = 0; mt < 2; mt++) {
        #pragma unroll
        for (int nt = 0; nt < 8; nt++) {
            const int col = colb + wn + nt * 8 + tg * 2;
            const float2 bv = *(const float2*)(b_proj + col);
            const long r1 = row0 + wm + mt * 16 + gq;
            *(float2*)(out + r1 * NC + col) =
                make_float2(acc[mt][nt][0] + bv.x, acc[mt][nt][1] + bv.y);
            *(float2*)(out + (r1 + 8) * NC + col) =
                make_float2(acc[mt][nt][2] + bv.x, acc[mt][nt][3] + bv.y);
        }
    }
}

// ---------------------------------------------------------------------------
extern "C" void kernel_launch(void* const* d_in, const int* in_sizes, int n_in,
                              void* d_out, int out_size)
{
    const float* x      = (const float*)d_in[0];
    const float* query  = (const float*)d_in[1];
    const float* W_qk   = (const float*)d_in[2];
    const float* W_v    = (const float*)d_in[3];
    const float* W_proj = (const float*)d_in[4];
    const float* b_proj = (const float*)d_in[5];
    const float* W_pre  = (const float*)d_in[6];
    const float* W_post = (const float*)d_in[7];
    float* out = (float*)d_out;

    cudaFuncSetAttribute(qkv_mma,  cudaFuncAttributeMaxDynamicSharedMemorySize, SMEM_MMA_BYTES);
    cudaFuncSetAttribute(attn_kernel, cudaFuncAttributeMaxDynamicSharedMemorySize, SMEM_ATTN_BYTES);
    cudaFuncSetAttribute(proj_mma, cudaFuncAttributeMaxDynamicSharedMemorySize, SMEM_MMA_BYTES);

    cvt_weights<<<128, 256>>>(W_qk, W_v, W_proj);
    qkv_mma<<<dim3(NWIN / 2, 6), 256, SMEM_MMA_BYTES>>>(x, query);
    attn_kernel<<<NWIN, 512, SMEM_ATTN_BYTES>>>(W_pre, W_post);
    proj_mma<<<dim3(NWIN / 2, 2), 256, SMEM_MMA_BYTES>>>(b_proj, out);
}

// round 7
// speedup vs baseline: 1.2298x; 1.0504x over previous
#include <cuda_runtime.h>
#include <cstdint>

// Problem constants
#define NB    8
#define NTOK  16384
#define NC    256
#define NWIN  2048    // B * (16x16 windows)
#define QKVW  768     // q(256) | k(256) | v(256)

// g_qkv channel dims stored PERMUTED within 8-groups:
// position p holds channel c(p) = (p&1)*4 + (p>>1)   (order 0,4,1,5,2,6,3,7)
__device__ float g_qkv[(size_t)NWIN * 64 * QKVW];
__device__ float g_wqk[512 * 256];     // rounded + permuted
__device__ float g_wv[256 * 256];
__device__ float g_wproj[256 * 256];

// ---------------------------------------------------------------------------
__device__ __forceinline__ uint32_t f2tf(float f) {
    uint32_t u;
    asm("cvt.rna.tf32.f32 %0, %1;" : "=r"(u) : "f"(f));
    return u;
}
__device__ __forceinline__ float ftf(float f) {
    return __uint_as_float(f2tf(f));
}
__device__ __forceinline__ void mma_tf32(float c[4],
    uint32_t a0, uint32_t a1, uint32_t a2, uint32_t a3,
    uint32_t b0, uint32_t b1)
{
    asm volatile(
        "mma.sync.aligned.m16n8k8.row.col.f32.tf32.tf32.f32 "
        "{%0,%1,%2,%3},{%4,%5,%6,%7},{%8,%9},{%0,%1,%2,%3};"
        : "+f"(c[0]), "+f"(c[1]), "+f"(c[2]), "+f"(c[3])
        : "r"(a0), "r"(a1), "r"(a2), "r"(a3), "r"(b0), "r"(b1));
}
#define CPA16(dst, src) \
    asm volatile("cp.async.cg.shared.global [%0],[%1],16;" :: "r"(dst), "l"(src))
#define CP_COMMIT() asm volatile("cp.async.commit_group;")
#define CP_WAIT0()  asm volatile("cp.async.wait_group 0;" ::: "memory")

// GEMM tiles: BM=128, BN=64, BK=32, 256 threads (8 warps of 32x32)
#define TS      36
#define ATILE_F (128 * TS)            // 4608
#define BTILE_F (64 * TS)             // 2304
#define BUF2_F  (ATILE_F + BTILE_F)   // 6912
#define SMEM_G2 (2 * BUF2_F * 4)      // 55296 B -> 4 CTAs/SM

// ---------------------------------------------------------------------------
// Weights: round to tf32 + permute 8-groups
// ---------------------------------------------------------------------------
__global__ __launch_bounds__(256) void cvt_weights(
    const float* __restrict__ wqk, const float* __restrict__ wv,
    const float* __restrict__ wproj)
{
    const int t = blockIdx.x * 256 + threadIdx.x;
    const int off = t * 8;
    const float* s; float* d;
    if (off < 131072)      { s = wqk + off;           d = g_wqk + off; }
    else if (off < 196608) { s = wv + off - 131072;   d = g_wv + off - 131072; }
    else                   { s = wproj + off - 196608; d = g_wproj + off - 196608; }
    float4 v0 = ((const float4*)s)[0], v1 = ((const float4*)s)[1];
    ((float4*)d)[0] = make_float4(ftf(v0.x), ftf(v1.x), ftf(v0.y), ftf(v1.y));
    ((float4*)d)[1] = make_float4(ftf(v0.z), ftf(v1.z), ftf(v0.w), ftf(v1.w));
}

// ---------------------------------------------------------------------------
// Kernel A: Q|K|V GEMM, 128x64 tile, 8 warps of 32x32. A raw (CVT frags),
// B permuted/rounded (float2 frags). g_qkv written rounded + permuted.
// blockIdx.y = 64-col block: 0..7 -> W_qk, 8..11 -> W_v
// ---------------------------------------------------------------------------
__global__ __launch_bounds__(256, 4) void qkv_mma(
    const float* __restrict__ x, const float* __restrict__ query)
{
    extern __shared__ float sm[];
    const int tid = threadIdx.x;
    const int p   = blockIdx.x;     // 0..1023, 128-row tile
    const int cb  = blockIdx.y;     // 0..11

    const float* in = (cb < 8) ? query : x;
    const float* Wt = (cb < 8) ? (g_wqk + (long)cb * 64 * 256)
                               : (g_wv  + (long)(cb - 8) * 64 * 256);
    const int dstcol = (cb < 8) ? cb * 64 : 512 + (cb - 8) * 64;

    // A: 128 rows x 32k, 2 threads/row; B: 64 rows x 32k, 4 threads/row
    const int ldrA = tid >> 1, ldcA = (tid & 1) << 4;
    const int ldrB = tid >> 2, ldcB = (tid & 3) << 3;
    int win = p * 2 + (ldrA >> 6);
    int s   = ldrA & 63;
    int b   = win >> 8, g = win & 255;
    int n   = ((g >> 4) * 8 + (s >> 3)) * 128 + (g & 15) * 8 + (s & 7);
    const float* a_src0 = in + ((long)b * NTOK + n) * 256 + ldcA;
    const float* b_src0 = Wt + (long)ldrB * 256 + ldcB;

    uint32_t smem_base = (uint32_t)__cvta_generic_to_shared(sm);
    uint32_t a_dst0 = smem_base + (uint32_t)(ldrA * TS + ldcA) * 4;
    uint32_t b_dst0 = smem_base + (uint32_t)(ATILE_F + ldrB * TS + ldcB) * 4;

    const int lane = tid & 31, w = tid >> 5;
    const int wm = (w >> 1) * 32;      // 4 m-tiles
    const int wn = (w & 1) * 32;       // 2 n-tiles
    const int gq = lane >> 2, tg = lane & 3;

    float acc[2][4][4];
    #pragma unroll
    for (int mt = 0; mt < 2; mt++)
        #pragma unroll
        for (int nt = 0; nt < 4; nt++)
            #pragma unroll
            for (int q = 0; q < 4; q++) acc[mt][nt][q] = 0.f;

    {
        #pragma unroll
        for (int i = 0; i < 4; i++) CPA16(a_dst0 + i * 16, a_src0 + i * 4);
        #pragma unroll
        for (int i = 0; i < 2; i++) CPA16(b_dst0 + i * 16, b_src0 + i * 4);
        CP_COMMIT();
    }

    for (int kb = 0; kb < 8; ++kb) {
        CP_WAIT0();
        __syncthreads();
        if (kb < 7) {
            uint32_t off = (uint32_t)(((kb + 1) & 1) * BUF2_F * 4);
            const float* as = a_src0 + (kb + 1) * 32;
            const float* bs = b_src0 + (kb + 1) * 32;
            #pragma unroll
            for (int i = 0; i < 4; i++) CPA16(a_dst0 + off + i * 16, as + i * 4);
            #pragma unroll
            for (int i = 0; i < 2; i++) CPA16(b_dst0 + off + i * 16, bs + i * 4);
            CP_COMMIT();
        }
        const float* sA = sm + (kb & 1) * BUF2_F;
        const float* sB = sA + ATILE_F;

        #pragma unroll
        for (int ks = 0; ks < 4; ++ks) {
            const int k0n = ks * 8;            // natural channels (A)
            const int k0p = ks * 8 + 2 * tg;   // permuted positions (B)
            uint32_t af[2][4];
            #pragma unroll
            for (int mt = 0; mt < 2; mt++) {
                const int r0 = wm + mt * 16;
                af[mt][0] = f2tf(sA[(r0 + gq)     * TS + k0n + tg]);
                af[mt][1] = f2tf(sA[(r0 + gq + 8) * TS + k0n + tg]);
                af[mt][2] = f2tf(sA[(r0 + gq)     * TS + k0n + tg + 4]);
                af[mt][3] = f2tf(sA[(r0 + gq + 8) * TS + k0n + tg + 4]);
            }
            #pragma unroll
            for (int nt = 0; nt < 4; nt++) {
                float2 bv = *(const float2*)&sB[(wn + nt * 8 + gq) * TS + k0p];
                uint32_t b0 = __float_as_uint(bv.x);   // channel k0n+tg
                uint32_t b1 = __float_as_uint(bv.y);   // channel k0n+tg+4
                mma_tf32(acc[0][nt], af[0][0], af[0][1], af[0][2], af[0][3], b0, b1);
                mma_tf32(acc[1][nt], af[1][0], af[1][1], af[1][2], af[1][3], b0, b1);
            }
        }
    }

    // natural out channels (2tg,2tg+1) -> permuted positions (pb,pb+2)
    const long row0 = (long)p * 128;
    const int pb = (tg & 1) * 4 + (tg >> 1);
    #pragma unroll
    for (int mt = 0; mt < 2; mt++) {
        #pragma unroll
        for (int nt = 0; nt < 4; nt++) {
            const int gb = dstcol + wn + nt * 8;
            const long r1 = row0 + wm + mt * 16 + gq;
            g_qkv[r1 * QKVW + gb + pb]           = ftf(acc[mt][nt][0]);
            g_qkv[r1 * QKVW + gb + pb + 2]       = ftf(acc[mt][nt][1]);
            g_qkv[(r1 + 8) * QKVW + gb + pb]     = ftf(acc[mt][nt][2]);
            g_qkv[(r1 + 8) * QKVW + gb + pb + 2] = ftf(acc[mt][nt][3]);
        }
    }
}

// ---------------------------------------------------------------------------
// Kernel B: attention, one block per (window, q-half). 256 thr, warp = head.
// Q/K/V fragments loaded DIRECTLY from g_qkv (no smem staging; no reuse
// outside the owning warps). smem holds only score planes (69 KB).
// ---------------------------------------------------------------------------
#define PL2 2116            // plane stride (>= 32*66; mod 32 == 4)
#define RS  66
#define OFF_WPRE  (8 * PL2)             // 16928
#define OFF_WPOST (OFF_WPRE + 64)
#define OFF_RSUM  (OFF_WPRE + 128)
#define SMEM_ATTN_F (OFF_RSUM + 256)    // 17312 floats
#define SMEM_ATTN_BYTES (SMEM_ATTN_F * 4)

__global__ __launch_bounds__(256) void attn_kernel(
    const float* __restrict__ W_pre, const float* __restrict__ W_post)
{
    extern __shared__ float sm[];
    float* s_attn  = sm;
    float* s_wpre  = sm + OFF_WPRE;
    float* s_wpost = sm + OFF_WPOST;
    float* s_rsum  = sm + OFF_RSUM;

    const int tid  = threadIdx.x;
    const int lane = tid & 31;
    const int h    = tid >> 5;                  // warp = head
    const int gq = lane >> 2, tg = lane & 3;
    const int h32 = h * 32;
    const int win = blockIdx.x >> 1;
    const int qb  = (blockIdx.x & 1) * 32;      // q-half
    const long rowbase = (long)win * 64;
    const float* gq_base = g_qkv + rowbase * QKVW;

    if (tid < 64) { s_wpre[tid] = W_pre[tid]; s_wpost[tid] = W_post[tid]; }

    // ---- scores: S_h[qb..qb+32] = Q_h @ K_h^T (M=32,N=64,K=32) — direct LDG
    float acc[2][8][4];
    #pragma unroll
    for (int mt = 0; mt < 2; mt++)
        #pragma unroll
        for (int nt = 0; nt < 8; nt++)
            #pragma unroll
            for (int q = 0; q < 4; q++) acc[mt][nt][q] = 0.f;

    #pragma unroll
    for (int ks = 0; ks < 4; ++ks) {
        const int k0p = h32 + ks * 8 + 2 * tg;   // permuted position
        uint32_t a[2][4];
        #pragma unroll
        for (int mt = 0; mt < 2; mt++) {
            const int r0 = qb + mt * 16;
            float2 lo = *(const float2*)(gq_base + (long)(r0 + gq)     * QKVW + k0p);
            float2 hi = *(const float2*)(gq_base + (long)(r0 + gq + 8) * QKVW + k0p);
            a[mt][0] = __float_as_uint(lo.x);
            a[mt][1] = __float_as_uint(hi.x);
            a[mt][2] = __float_as_uint(lo.y);
            a[mt][3] = __float_as_uint(hi.y);
        }
        #pragma unroll
        for (int nt = 0; nt < 8; nt++) {
            float2 bv = *(const float2*)(gq_base + (long)(nt * 8 + gq) * QKVW + 256 + k0p);
            uint32_t b0 = __float_as_uint(bv.x);
            uint32_t b1 = __float_as_uint(bv.y);
            #pragma unroll
            for (int mt = 0; mt < 2; mt++)
                mma_tf32(acc[mt][nt], a[mt][0], a[mt][1], a[mt][2], a[mt][3], b0, b1);
        }
    }

    // STS scaled scores into plane h (local q = 0..31)
    const float scale = 0.17677669529663687f;
    float* pl = s_attn + h * PL2;
    #pragma unroll
    for (int mt = 0; mt < 2; mt++) {
        #pragma unroll
        for (int nt = 0; nt < 8; nt++) {
            const int q0 = mt * 16 + gq, c = nt * 8 + 2 * tg;
            *(float2*)&pl[q0 * RS + c] =
                make_float2(acc[mt][nt][0] * scale, acc[mt][nt][1] * scale);
            *(float2*)&pl[(q0 + 8) * RS + c] =
                make_float2(acc[mt][nt][2] * scale, acc[mt][nt][3] * scale);
        }
    }
    __syncthreads();

    // ---- pre-mix + exp (2048 (q,k) pairs / 256 threads) ----
    #pragma unroll 1
    for (int i = 0; i < 8; i++) {
        int pidx = tid + (i << 8);
        int q = pidx >> 6, k = pidx & 63;
        float av[8], m[8];
        #pragma unroll
        for (int hh = 0; hh < 8; hh++) av[hh] = s_attn[hh * PL2 + q * RS + k];
        #pragma unroll
        for (int hh = 0; hh < 8; hh++) {
            float s = 0.f;
            #pragma unroll
            for (int h2 = 0; h2 < 8; h2++) s += av[h2] * s_wpre[hh * 8 + h2];
            m[hh] = __expf(s);
        }
        #pragma unroll
        for (int hh = 0; hh < 8; hh++) s_attn[hh * PL2 + q * RS + k] = m[hh];
    }
    __syncthreads();

    // ---- softmax denominator (256 tasks = 32q x 8h) ----
    {
        int q = tid >> 3, hh = tid & 7;
        float s = 0.f;
        #pragma unroll 8
        for (int k = 0; k < 64; k++) s += s_attn[hh * PL2 + q * RS + k];
        s_rsum[tid] = 1.0f / s;
    }
    __syncthreads();

    // ---- normalize + post-mix ----
    #pragma unroll 1
    for (int i = 0; i < 8; i++) {
        int pidx = tid + (i << 8);
        int q = pidx >> 6, k = pidx & 63;
        float av[8], m[8];
        #pragma unroll
        for (int hh = 0; hh < 8; hh++)
            av[hh] = s_attn[hh * PL2 + q * RS + k] * s_rsum[q * 8 + hh];
        #pragma unroll
        for (int hh = 0; hh < 8; hh++) {
            float s = 0.f;
            #pragma unroll
            for (int h2 = 0; h2 < 8; h2++) s += av[h2] * s_wpost[hh * 8 + h2];
            m[hh] = s;
        }
        #pragma unroll
        for (int hh = 0; hh < 8; hh++) s_attn[hh * PL2 + q * RS + k] = m[hh];
    }
    __syncthreads();

    // ---- O_h = A_h @ V_h (M=32,N=32,K=64) — V via direct LDG (rounded) ----
    float acc2[2][4][4];
    #pragma unroll
    for (int mt = 0; mt < 2; mt++)
        #pragma unroll
        for (int nt = 0; nt < 4; nt++)
            #pragma unroll
            for (int q = 0; q < 4; q++) acc2[mt][nt][q] = 0.f;

    #pragma unroll
    for (int ks = 0; ks < 8; ++ks) {
        const int k0 = ks * 8;
        uint32_t a[2][4];
        #pragma unroll
        for (int mt = 0; mt < 2; mt++) {
            const int r0 = mt * 16;
            a[mt][0] = f2tf(pl[(r0 + gq)     * RS + k0 + tg]);
            a[mt][1] = f2tf(pl[(r0 + gq + 8) * RS + k0 + tg]);
            a[mt][2] = f2tf(pl[(r0 + gq)     * RS + k0 + tg + 4]);
            a[mt][3] = f2tf(pl[(r0 + gq + 8) * RS + k0 + tg + 4]);
        }
        #pragma unroll
        for (int nt = 0; nt < 4; nt++) {
            const int nb = nt * 8;
            uint32_t b0 = __float_as_uint(
                gq_base[(long)(k0 + tg)     * QKVW + 512 + h32 + nb + gq]);
            uint32_t b1 = __float_as_uint(
                gq_base[(long)(k0 + tg + 4) * QKVW + 512 + h32 + nb + gq]);
            #pragma unroll
            for (int mt = 0; mt < 2; mt++)
                mma_tf32(acc2[mt][nt], a[mt][0], a[mt][1], a[mt][2], a[mt][3], b0, b1);
        }
    }

    // V indexed by storage POSITION -> output already permuted space
    #pragma unroll
    for (int mt = 0; mt < 2; mt++) {
        #pragma unroll
        for (int nt = 0; nt < 4; nt++) {
            const int col = h32 + nt * 8 + 2 * tg;
            const long r1 = rowbase + qb + mt * 16 + gq;
            *(float2*)(g_qkv + r1 * QKVW + col) =
                make_float2(ftf(acc2[mt][nt][0]), ftf(acc2[mt][nt][1]));
            *(float2*)(g_qkv + (r1 + 8) * QKVW + col) =
                make_float2(ftf(acc2[mt][nt][2]), ftf(acc2[mt][nt][3]));
        }
    }
}

// ---------------------------------------------------------------------------
// Kernel C: out = unwindow(O) @ W_proj^T + b_proj, 128x64 tile, zero CVT.
// ---------------------------------------------------------------------------
__global__ __launch_bounds__(256, 4) void proj_mma(
    const float* __restrict__ b_proj, float* __restrict__ out)
{
    extern __shared__ float sm[];
    const int tid = threadIdx.x;
    const long row0 = (long)blockIdx.x * 128;
    const int colb = blockIdx.y * 64;

    const int ldrA = tid >> 1, ldcA = (tid & 1) << 4;
    const int ldrB = tid >> 2, ldcB = (tid & 3) << 3;
    long row = row0 + ldrA;
    int b = (int)(row >> 14);
    int n = (int)(row & 16383);
    int i = n >> 7, j = n & 127;
    int srcrow = ((b << 8) + (i >> 3) * 16 + (j >> 3)) * 64 + (i & 7) * 8 + (j & 7);
    const float* a_src0 = g_qkv + (long)srcrow * QKVW + ldcA;
    const float* b_src0 = g_wproj + (long)(colb + ldrB) * 256 + ldcB;

    uint32_t smem_base = (uint32_t)__cvta_generic_to_shared(sm);
    uint32_t a_dst0 = smem_base + (uint32_t)(ldrA * TS + ldcA) * 4;
    uint32_t b_dst0 = smem_base + (uint32_t)(ATILE_F + ldrB * TS + ldcB) * 4;

    const int lane = tid & 31, w = tid >> 5;
    const int wm = (w >> 1) * 32;
    const int wn = (w & 1) * 32;
    const int gq = lane >> 2, tg = lane & 3;

    float acc[2][4][4];
    #pragma unroll
    for (int mt = 0; mt < 2; mt++)
        #pragma unroll
        for (int nt = 0; nt < 4; nt++)
            #pragma unroll
            for (int q = 0; q < 4; q++) acc[mt][nt][q] = 0.f;

    {
        #pragma unroll
        for (int k = 0; k < 4; k++) CPA16(a_dst0 + k * 16, a_src0 + k * 4);
        #pragma unroll
        for (int k = 0; k < 2; k++) CPA16(b_dst0 + k * 16, b_src0 + k * 4);
        CP_COMMIT();
    }

    for (int kb = 0; kb < 8; ++kb) {
        CP_WAIT0();
        __syncthreads();
        if (kb < 7) {
            uint32_t off = (uint32_t)(((kb + 1) & 1) * BUF2_F * 4);
            const float* as = a_src0 + (kb + 1) * 32;
            const float* bs = b_src0 + (kb + 1) * 32;
            #pragma unroll
            for (int k = 0; k < 4; k++) CPA16(a_dst0 + off + k * 16, as + k * 4);
            #pragma unroll
            for (int k = 0; k < 2; k++) CPA16(b_dst0 + off + k * 16, bs + k * 4);
            CP_COMMIT();
        }
        const float* sA = sm + (kb & 1) * BUF2_F;
        const float* sB = sA + ATILE_F;

        #pragma unroll
        for (int ks = 0; ks < 4; ++ks) {
            const int k0 = ks * 8 + 2 * tg;   // positions (both sides permuted)
            uint32_t af[2][4];
            #pragma unroll
            for (int mt = 0; mt < 2; mt++) {
                const int r0 = wm + mt * 16;
                float2 lo = *(const float2*)&sA[(r0 + gq)     * TS + k0];
                float2 hi = *(const float2*)&sA[(r0 + gq + 8) * TS + k0];
                af[mt][0] = __float_as_uint(lo.x);
                af[mt][1] = __float_as_uint(hi.x);
                af[mt][2] = __float_as_uint(lo.y);
                af[mt][3] = __float_as_uint(hi.y);
            }
            #pragma unroll
            for (int nt = 0; nt < 4; nt++) {
                float2 bv = *(const float2*)&sB[(wn + nt * 8 + gq) * TS + k0];
                uint32_t b0 = __float_as_uint(bv.x);
                uint32_t b1 = __float_as_uint(bv.y);
                mma_tf32(acc[0][nt], af[0][0], af[0][1], af[0][2], af[0][3], b0, b1);
                mma_tf32(acc[1][nt], af[1][0], af[1][1], af[1][2], af[1][3], b0, b1);
            }
        }
    }

    #pragma unroll
    for (int mt = 0; mt < 2; mt++) {
        #pragma unroll
        for (int nt = 0; nt < 4; nt++) {
            const int col = colb + wn + nt * 8 + tg * 2;
            const float2 bv = *(const float2*)(b_proj + col);
            const long r1 = row0 + wm + mt * 16 + gq;
            *(float2*)(out + r1 * NC + col) =
                make_float2(acc[mt][nt][0] + bv.x, acc[mt][nt][1] + bv.y);
            *(float2*)(out + (r1 + 8) * NC + col) =
                make_float2(acc[mt][nt][2] + bv.x, acc[mt][nt][3] + bv.y);
        }
    }
}

// ---------------------------------------------------------------------------
extern "C" void kernel_launch(void* const* d_in, const int* in_sizes, int n_in,
                              void* d_out, int out_size)
{
    const float* x      = (const float*)d_in[0];
    const float* query  = (const float*)d_in[1];
    const float* W_qk   = (const float*)d_in[2];
    const float* W_v    = (const float*)d_in[3];
    const float* W_proj = (const float*)d_in[4];
    const float* b_proj = (const float*)d_in[5];
    const float* W_pre  = (const float*)d_in[6];
    const float* W_post = (const float*)d_in[7];
    float* out = (float*)d_out;

    cudaFuncSetAttribute(qkv_mma,  cudaFuncAttributeMaxDynamicSharedMemorySize, SMEM_G2);
    cudaFuncSetAttribute(attn_kernel, cudaFuncAttributeMaxDynamicSharedMemorySize, SMEM_ATTN_BYTES);
    cudaFuncSetAttribute(proj_mma, cudaFuncAttributeMaxDynamicSharedMemorySize, SMEM_G2);

    cvt_weights<<<128, 256>>>(W_qk, W_v, W_proj);
    qkv_mma<<<dim3(1024, 12), 256, SMEM_G2>>>(x, query);
    attn_kernel<<<NWIN * 2, 256, SMEM_ATTN_BYTES>>>(W_pre, W_post);
    proj_mma<<<dim3(1024, 4), 256, SMEM_G2>>>(b_proj, out);
}